// round 14
// baseline (speedup 1.0000x reference)
#include <cuda_runtime.h>

#define NN 128
#define TT 2048
#define DD 88
#define D4 22                  // float4 per row
#define NWORDS (NN * TT / 2)   // 131072 warp-words (1024 per n)
#define BLK_PER_N 128          // 16 rows per block

__device__ unsigned int g_w[NWORDS];       // f0 | f1<<8 | tp<<16 | ti<<26
__device__ unsigned int g_cnt[NN * 64];    // per-n arrival counters, 256B stride
__device__ float        g_acc[NN];
__device__ unsigned int g_done = 0;

__global__ void __launch_bounds__(256, 8) fused_accuracy(
    const float4* __restrict__ outp,
    const float4* __restrict__ tgtp,
    const int*    __restrict__ mask,
    float*        __restrict__ out)
{
    const int tid  = threadIdx.x;
    const int warp = tid >> 5;
    const int lane = tid & 31;
    const int w    = blockIdx.x * 8 + warp;    // global warp-word index
    const int n    = blockIdx.x >> 7;          // 128 blocks per n
    const int r0   = w * 2;

    // ---------------- streaming body (identical to R13 k1) ----------------
    const size_t base = (size_t)r0 * D4 + lane;
    const bool   act  = (lane < D4);

    float4 o0, o1, g0, g1;
    if (act) {
        o0 = __ldcs(outp + base);
        o1 = __ldcs(outp + base + D4);
        g0 = __ldcs(tgtp + base);
        g1 = __ldcs(tgtp + base + D4);
    }
    unsigned int v = 0;
    if (lane == D4)     v = ((unsigned)mask[r0])     << 26;
    if (lane == D4 + 1) v = ((unsigned)mask[r0 + 1]) << 26;

    if (act) {
        int f0 = 0, f1 = 0, tp = 0;
        #define ELEM(ov, gv, fv) {                    \
            const bool p = ((ov) > 0.f);              \
            const bool q = ((gv) != 0.f);             \
            tp += (p && q) ? 1 : 0;                   \
            fv += (p != q) ? 1 : 0; }
        ELEM(o0.x, g0.x, f0) ELEM(o0.y, g0.y, f0) ELEM(o0.z, g0.z, f0) ELEM(o0.w, g0.w, f0)
        ELEM(o1.x, g1.x, f1) ELEM(o1.y, g1.y, f1) ELEM(o1.z, g1.z, f1) ELEM(o1.w, g1.w, f1)
        #undef ELEM
        v = (unsigned)f0 | ((unsigned)f1 << 8) | ((unsigned)tp << 16);
    }

    #pragma unroll
    for (int off = 16; off; off >>= 1)
        v += __shfl_down_sync(0xffffffffu, v, off);

    if (lane == 0) g_w[w] = v;

    // ---------------- arrival: last block of this n becomes finisher ------
    __shared__ int s_role;
    __syncthreads();                       // all warps' STGs issued
    if (tid == 0) {
        __threadfence();                   // release g_w stores
        unsigned int old = atomicAdd(&g_cnt[n << 6], 1u);
        s_role = (old == BLK_PER_N - 1) ? 1 : 0;
        if (s_role) g_cnt[n << 6] = 0;     // reset for next graph replay
    }
    __syncthreads();
    if (!s_role) return;

    // ================= finisher for sequence n (L2-hot) ====================
    __threadfence();                       // acquire

    __shared__ unsigned int s_i[8];
    __shared__ float        s_f[8];
    __shared__ int          s_last;

    const uint4 wv = ((const uint4*)g_w)[n * 256 + tid];   // 4 words = 8 rows

    unsigned int tps = ((wv.x >> 16) & 0x3ffu) + ((wv.y >> 16) & 0x3ffu)
                     + ((wv.z >> 16) & 0x3ffu) + ((wv.w >> 16) & 0x3ffu);
    unsigned int tis = (wv.x >> 26) + (wv.y >> 26) + (wv.z >> 26) + (wv.w >> 26);
    unsigned int pk  = tps | (tis << 18);
    #pragma unroll
    for (int off = 16; off; off >>= 1)
        pk += __shfl_down_sync(0xffffffffu, pk, off);
    if (lane == 0) s_i[warp] = pk;
    __syncthreads();
    const unsigned tot = s_i[0] + s_i[1] + s_i[2] + s_i[3]
                       + s_i[4] + s_i[5] + s_i[6] + s_i[7];
    const float tpf = (float)(tot & 0x3ffffu);
    const int   Ti  = (int)(tot >> 18);

    const int tb = tid * 8;
    float acc = 0.f;
    #define RAT(word, k) {                                                  \
        if (tb + 2*(k)     < Ti) acc += __fdividef(tpf, tpf + (float)( (word)        & 0xffu)); \
        if (tb + 2*(k) + 1 < Ti) acc += __fdividef(tpf, tpf + (float)(((word) >> 8)  & 0xffu)); }
    RAT(wv.x, 0) RAT(wv.y, 1) RAT(wv.z, 2) RAT(wv.w, 3)
    #undef RAT

    #pragma unroll
    for (int off = 16; off; off >>= 1)
        acc += __shfl_down_sync(0xffffffffu, acc, off);
    if (lane == 0) s_f[warp] = acc;
    __syncthreads();

    if (tid == 0) {
        float v8 = s_f[0] + s_f[1] + s_f[2] + s_f[3]
                 + s_f[4] + s_f[5] + s_f[6] + s_f[7];
        g_acc[n] = v8 / (float)Ti;
        __threadfence();
        unsigned int old = atomicAdd(&g_done, 1u);
        s_last = (old == NN - 1) ? 1 : 0;
    }
    __syncthreads();
    if (!s_last) return;

    // ================= global finisher: fixed-order 128-way sum ===========
    if (warp == 0) {
        __threadfence();
        float vv = g_acc[lane] + g_acc[lane + 32] + g_acc[lane + 64] + g_acc[lane + 96];
        #pragma unroll
        for (int off = 16; off; off >>= 1)
            vv += __shfl_down_sync(0xffffffffu, vv, off);
        if (lane == 0) {
            out[0]  = vv;
            g_done = 0;        // reset for next graph replay
        }
    }
}

extern "C" void kernel_launch(void* const* d_in, const int* in_sizes, int n_in,
                              void* d_out, int out_size)
{
    const float4* outp = (const float4*)d_in[0];
    const float4* tgtp = (const float4*)d_in[1];
    const int*    mask = (const int*)  d_in[2];
    float*        out  = (float*)d_out;

    fused_accuracy<<<NWORDS / 8, 256>>>(outp, tgtp, mask, out);  // 16384 blocks
}

// round 15
// speedup vs baseline: 1.1654x; 1.1654x over previous
#include <cuda_runtime.h>

#define NN 128
#define TT 2048
#define DD 88
#define D4 22                  // float4 per row
#define NWORDS (NN * TT / 2)   // 131072 warp-words (1024 per n)

__device__ unsigned int g_w[NWORDS];       // f0 | f1<<8 | tp<<16 | ti<<26
__device__ unsigned int g_stat[NN * 64];   // per-n: tp_tot | Ti<<18  (256B stride)
__device__ float        g_acc[NN];
__device__ unsigned int g_done = 0;

// ---------------------------------------------------------------------------
// k1: one warp per 2 rows (R13 body, zero inter-warp coupling).
// Epilogue: lane 0 stores the packed word AND fires one no-return RED
// accumulating tp|Ti into the per-n stat word.
// ---------------------------------------------------------------------------
__global__ void __launch_bounds__(256) k1_rowstats(
    const float4* __restrict__ outp,
    const float4* __restrict__ tgtp,
    const int*    __restrict__ mask)
{
    const int w    = blockIdx.x * 8 + (threadIdx.x >> 5);  // global warp id
    const int lane = threadIdx.x & 31;
    const int r0   = w * 2;

    const size_t base = (size_t)r0 * D4 + lane;
    const bool   act  = (lane < D4);

    float4 o0, o1, g0, g1;
    if (act) {
        o0 = __ldcs(outp + base);
        o1 = __ldcs(outp + base + D4);
        g0 = __ldcs(tgtp + base);
        g1 = __ldcs(tgtp + base + D4);
    }
    unsigned int v = 0;
    if (lane == D4)     v = ((unsigned)mask[r0])     << 26;
    if (lane == D4 + 1) v = ((unsigned)mask[r0 + 1]) << 26;

    if (act) {
        int f0 = 0, f1 = 0, tp = 0;
        #define ELEM(ov, gv, fv) {                    \
            const bool p = ((ov) > 0.f);              \
            const bool q = ((gv) != 0.f);             \
            tp += (p && q) ? 1 : 0;                   \
            fv += (p != q) ? 1 : 0; }
        ELEM(o0.x, g0.x, f0) ELEM(o0.y, g0.y, f0) ELEM(o0.z, g0.z, f0) ELEM(o0.w, g0.w, f0)
        ELEM(o1.x, g1.x, f1) ELEM(o1.y, g1.y, f1) ELEM(o1.z, g1.z, f1) ELEM(o1.w, g1.w, f1)
        #undef ELEM
        v = (unsigned)f0 | ((unsigned)f1 << 8) | ((unsigned)tp << 16);
    }

    // one short reduce: field maxima f0=88, f1=88, tp=176, ti=2 -> no carry
    #pragma unroll
    for (int off = 16; off; off >>= 1)
        v += __shfl_down_sync(0xffffffffu, v, off);

    if (lane == 0) {
        g_w[w] = v;
        const unsigned tpw = (v >> 16) & 0x3ffu;
        const unsigned tiw = (v >> 26);
        const int n = w >> 10;
        atomicAdd(&g_stat[n << 6], tpw + (tiw << 18));   // no-return RED
    }
}

// ---------------------------------------------------------------------------
// k2: one block (1024 thr) per n. tp/Ti already totalled -> both loads issue
// in parallel, divides start right after. One acc-reduce, fused final.
// ---------------------------------------------------------------------------
__global__ void __launch_bounds__(1024) k2_finish(float* __restrict__ out)
{
    const int n    = blockIdx.x;
    const int tid  = threadIdx.x;
    const int warp = tid >> 5;
    const int lane = tid & 31;

    __shared__ float s_f[32];
    __shared__ int   s_last;

    // two independent loads, issued back-to-back
    const unsigned int w    = g_w[n * 1024 + tid];
    const unsigned int stat = g_stat[n << 6];

    const float tpf = (float)(stat & 0x3ffffu);
    const int   Ti  = (int)(stat >> 18);

    float acc = 0.f;
    if (2 * tid     < Ti) acc += __fdividef(tpf, tpf + (float)( w       & 0xffu));
    if (2 * tid + 1 < Ti) acc += __fdividef(tpf, tpf + (float)((w >> 8) & 0xffu));

    #pragma unroll
    for (int off = 16; off; off >>= 1)
        acc += __shfl_down_sync(0xffffffffu, acc, off);
    if (lane == 0) s_f[warp] = acc;
    __syncthreads();

    if (tid == 0) g_stat[n << 6] = 0;      // reset for next graph replay

    if (warp == 0) {
        float a = s_f[lane];
        #pragma unroll
        for (int off = 16; off; off >>= 1)
            a += __shfl_down_sync(0xffffffffu, a, off);
        if (lane == 0) g_acc[n] = a / (float)Ti;
    }

    // ---- fused deterministic final reduction ----
    if (tid == 0) {
        __threadfence();
        unsigned int old = atomicAdd(&g_done, 1u);
        s_last = (old == (unsigned)(gridDim.x - 1)) ? 1 : 0;
    }
    __syncthreads();
    if (s_last && warp == 0) {
        __threadfence();
        float vv = g_acc[lane] + g_acc[lane + 32] + g_acc[lane + 64] + g_acc[lane + 96];
        #pragma unroll
        for (int off = 16; off; off >>= 1)
            vv += __shfl_down_sync(0xffffffffu, vv, off);
        if (lane == 0) {
            out[0]  = vv;
            g_done = 0;        // reset for next graph replay
        }
    }
}

extern "C" void kernel_launch(void* const* d_in, const int* in_sizes, int n_in,
                              void* d_out, int out_size)
{
    const float4* outp = (const float4*)d_in[0];
    const float4* tgtp = (const float4*)d_in[1];
    const int*    mask = (const int*)  d_in[2];
    float*        out  = (float*)d_out;

    k1_rowstats<<<NWORDS / 8, 256>>>(outp, tgtp, mask);   // 16384 blocks
    k2_finish<<<NN, 1024>>>(out);
}